// round 17
// baseline (speedup 1.0000x reference)
#include <cuda_runtime.h>

// Problem constants
#define BS   64
#define SEQ  512
#define H    768
#define TT   64   // topic count per batch
#define KK   64   // token count per batch

#define RPB      8            // rows per row-block
#define THREADS  256
#define NROWBLK  17           // row blocks per batch (8 topic + 8 token + 1 cls)

// g_A[b][m][p]: m in {cls_c0, cls_c1, topic_c0, topic_c1, token_c0, token_c1}
__device__ float4 g_A4[BS * 6 * H / 4];
__device__ int    g_ready[BS];   // builders done count (0..6), reset each run
__device__ int    g_done[BS];    // consumer count (0..17), reset each run

// Dynamic smem: row blocks: sA[2*768] + sH[8*768] = 30720 B
//               builders  : sW[6144] + d0[768]    = 27648 B  (overlaid)
#define SMEM_BYTES ((2 * H + RPB * H) * 4)

__device__ __forceinline__ int ld_acquire_gpu(const int* p) {
    int v;
    asm volatile("ld.acquire.gpu.global.b32 %0, [%1];"
                 : "=r"(v) : "l"(p) : "memory");
    return v;
}

// ---------------------------------------------------------------------------
// One fused kernel. grid = (BS, 23), 256 threads.
//   y in [0,5]  : builder block (b, m=y) — computes A[b][m][0..767], publishes.
//   y in [6,22] : row block ry=y-6: ry<8 topic, ry<16 token, ry==16 cls.
// Row blocks fire their cp.async gather before any dependency, then spin
// (acquire) on g_ready[b]==6, stage their one A pair, dot, epilogue.
// ---------------------------------------------------------------------------
__global__ void __launch_bounds__(THREADS) fused_kernel(
    const float* __restrict__ hidden,     // [BS, SEQ, H]
    const float* __restrict__ Wsrc,       // [862, 384]
    const float* __restrict__ Wtgt,       // [862, 384]
    const float* __restrict__ Wcls,       // [2, 6144]
    const float* __restrict__ Wtopic,     // [2, 6144]
    const float* __restrict__ Wtoken,     // [2, 6144]
    const float* __restrict__ b_cls,      // [2]
    const float* __restrict__ b_topic,    // [2]
    const float* __restrict__ b_token,    // [2]
    const int*   __restrict__ src_ids,    // [BS]
    const int*   __restrict__ tgt_ids,    // [BS]
    const int*   __restrict__ topic_inds, // [BS, TT]
    const float* __restrict__ topic_mask, // [BS, TT]
    const int*   __restrict__ token_inds, // [BS, KK]
    const float* __restrict__ token_mask, // [BS, KK]
    float* __restrict__ out)              // [128 | 8192 | 8192]
{
    const int b   = blockIdx.x;
    const int y   = blockIdx.y;            // 0..22
    const int tid = threadIdx.x;

    extern __shared__ float smem[];

    // =============================== BUILDER ==============================
    if (y < 6) {
        const int m = y;                   // 0..5
        float* sW = smem;                  // 6144
        float* d0 = smem + 6144;           // 768

        const int w = m >> 1;
        const int c = m & 1;
        const float4* __restrict__ Wb = (const float4*)(
            (w == 0 ? Wcls : (w == 1 ? Wtopic : Wtoken)) + c * 6144);

        {
            float4* sW4 = (float4*)sW;
#pragma unroll
            for (int e = tid; e < 1536; e += THREADS)
                sW4[e] = Wb[e];

            const float4* __restrict__ s =
                (const float4*)(Wsrc + (size_t)src_ids[b] * 384);
            const float4* __restrict__ t =
                (const float4*)(Wtgt + (size_t)tgt_ids[b] * 384);
            float4* d04 = (float4*)d0;
            if (tid < 96)       d04[tid]           = s[tid];
            else if (tid < 192) d04[tid - 96 + 96] = t[tid - 96];
        }
        __syncthreads();

        float* __restrict__ Ab = ((float*)g_A4) + ((size_t)b * 6 + m) * H;
#pragma unroll
        for (int e = tid; e < H; e += THREADS) {
            const int g = e >> 3;
            const int j = e & 7;
            const float* __restrict__ Wp = sW + g * 64 + j;
            const float* __restrict__ d  = d0 + g * 8;
            float acc = 0.f;
#pragma unroll
            for (int i = 0; i < 8; i++)
                acc = fmaf(d[i], Wp[i * 8], acc);
            Ab[e] = acc;
        }

        // Publish: every thread fences its own stores, barrier, one RMW.
        __threadfence();
        __syncthreads();
        if (tid == 0)
            atomicAdd(&g_ready[b], 1);
        return;
    }

    // ============================== ROW BLOCK =============================
    const int  ry       = y - 6;           // 0..16
    const bool is_cls   = (ry == 16);
    const bool is_topic = (ry < 8);
    const int  qoff     = (ry & 7) * RPB;
    const int  nrows    = is_cls ? 1 : RPB;
    const int  warp     = tid >> 5;
    const int  lane     = tid & 31;

    float* sA = smem;           // 2*768
    float* sH = smem + 2 * H;   // 8*768
    __shared__ int   sIdx[RPB];
    __shared__ float sMask[RPB];

    // ---- indices + masks -------------------------------------------------
    if (tid < nrows) {
        int idx; float mk;
        if (is_cls) {
            idx = 0; mk = 1.f;
        } else if (is_topic) {
            idx = topic_inds[b * TT + qoff + tid];
            mk  = topic_mask[b * TT + qoff + tid];
        } else {
            idx = token_inds[b * KK + qoff + tid];
            mk  = token_mask[b * KK + qoff + tid];
        }
        sIdx[tid]  = idx;
        sMask[tid] = mk;
    }
    __syncthreads();

    // ---- fire the DRAM gather (cp.async, warp-per-row) -------------------
    if (warp < nrows) {
        const float4* __restrict__ src =
            (const float4*)(hidden + ((size_t)b * SEQ + sIdx[warp]) * H) + lane;
        unsigned dst = (unsigned)__cvta_generic_to_shared(sH + warp * H)
                       + (unsigned)(lane * 16);
#pragma unroll
        for (int k = 0; k < 6; k++) {
            asm volatile("cp.async.cg.shared.global [%0], [%1], 16;\n"
                         :: "r"(dst + (unsigned)(k * 512)), "l"(src + k * 32));
        }
    }
    asm volatile("cp.async.commit_group;\n");

    // ---- wait for this batch's builders (fine-grained, overlaps gather) --
    if (tid == 0) {
        while (ld_acquire_gpu(&g_ready[b]) < 6)
            __nanosleep(64);
        // replay-safe reset: the 17th consumer of this batch clears both
        const int old = atomicAdd(&g_done[b], 1);
        if (old == NROWBLK - 1) {
            atomicExch(&g_done[b], 0);
            atomicExch(&g_ready[b], 0);
        }
    }
    __syncthreads();   // propagate acquired visibility CTA-wide

    // ---- stage this block's A pair from g_A (L2) -------------------------
    {
        const int m0 = is_cls ? 0 : (is_topic ? 2 : 4);
        const float4* __restrict__ Ap = g_A4 + ((size_t)b * 6 + m0) * (H / 4);
        float4* sA4 = (float4*)sA;
        for (int e = tid; e < 2 * H / 4; e += THREADS)
            sA4[e] = Ap[e];
    }
    __syncthreads();

    // ---- wait own gathered row, dot + epilogue ---------------------------
    asm volatile("cp.async.wait_group 0;\n");

    if (warp < nrows) {
        const float4* __restrict__ h4 = (const float4*)(sH + warp * H);
        const float4* __restrict__ a0 = (const float4*)sA;
        const float4* __restrict__ a1 = a0 + (H / 4);

        float acc0 = 0.f, acc1 = 0.f;
#pragma unroll
        for (int k = 0; k < 6; k++) {
            const int p = lane + k * 32;
            const float4 h = h4[p];
            const float4 x = a0[p];
            const float4 z = a1[p];
            acc0 = fmaf(h.x, x.x, fmaf(h.y, x.y, fmaf(h.z, x.z, fmaf(h.w, x.w, acc0))));
            acc1 = fmaf(h.x, z.x, fmaf(h.y, z.y, fmaf(h.z, z.z, fmaf(h.w, z.w, acc1))));
        }
#pragma unroll
        for (int o = 16; o; o >>= 1) {
            acc0 += __shfl_xor_sync(0xFFFFFFFFu, acc0, o);
            acc1 += __shfl_xor_sync(0xFFFFFFFFu, acc1, o);
        }

        if (lane == 0) {
            const float mask = sMask[warp];
            float bias0, bias1;
            float* outp;
            bool do_softmax;
            if (is_cls) {
                bias0 = b_cls[0]; bias1 = b_cls[1];
                outp = out + b * 2;
                do_softmax = true;
            } else if (is_topic) {
                bias0 = b_topic[0]; bias1 = b_topic[1];
                outp = out + 128 + (b * TT + qoff + warp) * 2;
                do_softmax = true;
            } else {
                bias0 = b_token[0]; bias1 = b_token[1];
                outp = out + 128 + BS * TT * 2 + (b * KK + qoff + warp) * 2;
                do_softmax = false;
            }

            const float x0 = fmaf(mask, acc0, bias0);
            const float x1 = fmaf(mask, acc1, bias1);
            if (do_softmax) {
                const float mx = fmaxf(x0, x1);
                const float e0 = __expf(x0 - mx);
                const float e1 = __expf(x1 - mx);
                const float inv = 1.f / (e0 + e1);
                outp[0] = e0 * inv;
                outp[1] = e1 * inv;
            } else {
                outp[0] = x0;
                outp[1] = x1;
            }
        }
    }
}

// ---------------------------------------------------------------------------
// Launch: ONE kernel. Builders are y=0..5 (first 384 blocks -> scheduled
// first, so the flag spin can never deadlock).
// ---------------------------------------------------------------------------
extern "C" void kernel_launch(void* const* d_in, const int* in_sizes, int n_in,
                              void* d_out, int out_size)
{
    const float* hidden     = (const float*)d_in[0];   // [64,512,768]
    const float* Wsrc       = (const float*)d_in[1];   // [862,384]
    const float* Wtgt       = (const float*)d_in[2];   // [862,384]
    const float* W_cls      = (const float*)d_in[3];   // [2,6144]
    const float* b_cls      = (const float*)d_in[4];   // [2]
    const float* W_topic    = (const float*)d_in[5];   // [2,6144]
    const float* b_topic    = (const float*)d_in[6];   // [2]
    const float* W_token    = (const float*)d_in[7];   // [2,6144]
    const float* b_token    = (const float*)d_in[8];   // [2]
    const int*   source_ids = (const int*)d_in[9];     // [64]
    const int*   target_ids = (const int*)d_in[10];    // [64]
    // d_in[11] ent_inds, d_in[12] ent_mask: unused by reference outputs
    const int*   topic_inds = (const int*)d_in[13];    // [64,64]
    const float* topic_mask = (const float*)d_in[14];  // [64,64]
    const int*   token_inds = (const int*)d_in[15];    // [64,64]
    const float* token_mask = (const float*)d_in[16];  // [64,64]

    float* out = (float*)d_out;

    cudaFuncSetAttribute(fused_kernel,
                         cudaFuncAttributeMaxDynamicSharedMemorySize,
                         SMEM_BYTES);

    fused_kernel<<<dim3(BS, 6 + NROWBLK), THREADS, SMEM_BYTES>>>(
        hidden, Wsrc, Wtgt, W_cls, W_topic, W_token,
        b_cls, b_topic, b_token,
        source_ids, target_ids,
        topic_inds, topic_mask, token_inds, token_mask, out);
}